// round 14
// baseline (speedup 1.0000x reference)
#include <cuda_runtime.h>
#include <cuda_bf16.h>
#include <cstdint>
#include <math.h>

#define SQ   4096
#define DIM  2048
#define HD   128
#define NH   16
#define NKV  4
#define KVD  512

// ---------------- device scratch ----------------
__device__ float g_qkv[(size_t)SQ * 3072];
__device__ __nv_bfloat16 g_xh[(size_t)SQ * DIM],  g_xl[(size_t)SQ * DIM];
__device__ __nv_bfloat16 g_qh[(size_t)SQ * DIM],  g_ql[(size_t)SQ * DIM];   // scaled by 1/sqrt(hd)*log2e
__device__ __nv_bfloat16 g_kh[(size_t)SQ * KVD],  g_kl[(size_t)SQ * KVD];
__device__ __nv_bfloat16 g_vth[(size_t)KVD * SQ], g_vtl[(size_t)KVD * SQ];  // V^T [d][t]
__device__ __nv_bfloat16 g_ah[(size_t)SQ * DIM],  g_al[(size_t)SQ * DIM];
__device__ __nv_bfloat16 g_wh[(size_t)3072 * DIM], g_wl[(size_t)3072 * DIM];
__device__ __nv_bfloat16 g_woh[(size_t)DIM * DIM], g_wol[(size_t)DIM * DIM];

// ---------------- helpers ----------------
__device__ __forceinline__ uint32_t smem_u32(const void* p) {
    uint32_t a;
    asm("{ .reg .u64 t; cvta.to.shared.u64 t, %1; cvt.u32.u64 %0, t; }" : "=r"(a) : "l"(p));
    return a;
}
__device__ __forceinline__ void ldm4(uint32_t* r, uint32_t addr) {
    asm volatile("ldmatrix.sync.aligned.m8n8.x4.shared.b16 {%0,%1,%2,%3}, [%4];"
                 : "=r"(r[0]), "=r"(r[1]), "=r"(r[2]), "=r"(r[3]) : "r"(addr));
}
__device__ __forceinline__ void mma16816(float* c, const uint32_t* a, uint32_t b0, uint32_t b1) {
    asm volatile(
        "mma.sync.aligned.m16n8k16.row.col.f32.bf16.bf16.f32 "
        "{%0,%1,%2,%3}, {%4,%5,%6,%7}, {%8,%9}, {%0,%1,%2,%3};"
        : "+f"(c[0]), "+f"(c[1]), "+f"(c[2]), "+f"(c[3])
        : "r"(a[0]), "r"(a[1]), "r"(a[2]), "r"(a[3]), "r"(b0), "r"(b1));
}
__device__ __forceinline__ float ex2f(float x) {
    float r; asm("ex2.approx.ftz.f32 %0, %1;" : "=f"(r) : "f"(x)); return r;
}
__device__ __forceinline__ void split2(float c0, float c1, uint32_t& hp, uint32_t& lp) {
    asm("cvt.rn.bf16x2.f32 %0, %1, %2;" : "=r"(hp) : "f"(c1), "f"(c0));
    float h0 = __uint_as_float(hp << 16);
    float h1 = __uint_as_float(hp & 0xffff0000u);
    float l0 = c0 - h0, l1 = c1 - h1;
    asm("cvt.rn.bf16x2.f32 %0, %1, %2;" : "=r"(lp) : "f"(l1), "f"(l0));
}
__device__ __forceinline__ void cpa16(uint32_t dst, const void* src) {
    asm volatile("cp.async.cg.shared.global [%0], [%1], 16;" :: "r"(dst), "l"(src));
}

// ---------------------------------------------------------------------------
// Split-bf16 GEMM, cp.async double-buffered: C[M,N] fp32 = (Ah+Al)*(Bh+Bl)^T
// (3 terms). 128x128 CTA tile, 8 warps (4m x 2n), BK=32, one sync per chunk.
// ---------------------------------------------------------------------------
#define PITCHB 80
#define OPB    (128 * PITCHB)
#define BUFB   (4 * OPB)
#define GEMM_SMEM (2 * BUFB)

__global__ __launch_bounds__(256) void gemm_tc(
    const __nv_bfloat16* __restrict__ Ah, const __nv_bfloat16* __restrict__ Al, int lda,
    const __nv_bfloat16* __restrict__ Bh, const __nv_bfloat16* __restrict__ Bl, int ldb,
    float* __restrict__ C, int ldc, int nk)
{
    extern __shared__ char smem[];
    const uint32_t sb = smem_u32(smem);
    const int tid = threadIdx.x, lane = tid & 31, wid = tid >> 5;
    const int wm = wid & 3, wn = wid >> 2;
    const int m0 = blockIdx.y * 128, n0 = blockIdx.x * 128;

    float acc[2][8][4];
    #pragma unroll
    for (int i = 0; i < 2; i++)
        #pragma unroll
        for (int j = 0; j < 8; j++)
            #pragma unroll
            for (int c = 0; c < 4; c++) acc[i][j][c] = 0.f;

    const __nv_bfloat16* OPS[4] = {Ah, Al, Bh, Bl};

    // cp.async one 32-col chunk of all 4 operand tiles into buffer BUF
    #define G_ISSUE(KC, BUF)                                                      \
        {                                                                         \
            const long long ko = (long long)(KC) * 32;                            \
            _Pragma("unroll")                                                     \
            for (int o = 0; o < 4; o++) {                                         \
                const __nv_bfloat16* P = OPS[o];                                  \
                const int ld_ = (o < 2) ? lda : ldb;                              \
                const int rb  = (o < 2) ? m0 : n0;                                \
                _Pragma("unroll")                                                 \
                for (int j = 0; j < 2; j++) {                                     \
                    int linear = tid + j * 256;                                   \
                    int row = linear >> 2, c4 = linear & 3;                       \
                    cpa16(sb + (BUF) * BUFB + o * OPB + row * PITCHB + c4 * 16,   \
                          P + (size_t)(rb + row) * ld_ + ko + c4 * 8);            \
                }                                                                 \
            }                                                                     \
            asm volatile("cp.async.commit_group;" ::: "memory");                  \
        }

    G_ISSUE(0, 0);

    for (int kc = 0; kc < nk; kc++) {
        const int cur = kc & 1;
        asm volatile("cp.async.wait_group 0;" ::: "memory");
        __syncthreads();                       // chunk kc visible; compute kc-1 done
        if (kc + 1 < nk) G_ISSUE(kc + 1, 1 - cur);

        const uint32_t base = sb + cur * BUFB;
        const uint32_t aHb = base + (uint32_t)((wm * 32 + (lane & 15)) * PITCHB + (lane >> 4) * 16);
        const uint32_t aLb = aHb + OPB;
        const uint32_t bRow = (uint32_t)(wn * 64 + (lane & 7) + ((lane >> 4) * 8));
        const uint32_t bHb = base + 2 * OPB + bRow * PITCHB + (((lane >> 3) & 1) * 16);
        const uint32_t bLb = bHb + OPB;

        #pragma unroll
        for (int ks = 0; ks < 2; ks++) {
            const uint32_t ko = ks * 32;
            uint32_t aH[2][4], aL[2][4], bH[4][4], bL[4][4];
            #pragma unroll
            for (int mt = 0; mt < 2; mt++) {
                ldm4(aH[mt], aHb + mt * (16 * PITCHB) + ko);
                ldm4(aL[mt], aLb + mt * (16 * PITCHB) + ko);
            }
            #pragma unroll
            for (int np = 0; np < 4; np++) {
                ldm4(bH[np], bHb + np * (16 * PITCHB) + ko);
                ldm4(bL[np], bLb + np * (16 * PITCHB) + ko);
            }
            #pragma unroll
            for (int mt = 0; mt < 2; mt++)
                #pragma unroll
                for (int np = 0; np < 4; np++) {
                    mma16816(acc[mt][2 * np],     aH[mt], bH[np][0], bH[np][1]);
                    mma16816(acc[mt][2 * np + 1], aH[mt], bH[np][2], bH[np][3]);
                    mma16816(acc[mt][2 * np],     aH[mt], bL[np][0], bL[np][1]);
                    mma16816(acc[mt][2 * np + 1], aH[mt], bL[np][2], bL[np][3]);
                    mma16816(acc[mt][2 * np],     aL[mt], bH[np][0], bH[np][1]);
                    mma16816(acc[mt][2 * np + 1], aL[mt], bH[np][2], bH[np][3]);
                }
        }
    }
    #undef G_ISSUE

    #pragma unroll
    for (int mt = 0; mt < 2; mt++)
        #pragma unroll
        for (int nt = 0; nt < 8; nt++) {
            const int r0 = m0 + wm * 32 + mt * 16 + (lane >> 2);
            const int cc = n0 + wn * 64 + nt * 8 + (lane & 3) * 2;
            *(float2*)&C[(size_t)r0 * ldc + cc]       = make_float2(acc[mt][nt][0], acc[mt][nt][1]);
            *(float2*)&C[(size_t)(r0 + 8) * ldc + cc] = make_float2(acc[mt][nt][2], acc[mt][nt][3]);
        }
}

// ---------------------------------------------------------------------------
// Flash attention (R9 config): 128-row q-tiles, 8 warps, 64-key K/V tiles,
// cp.async double-buffered.
// ---------------------------------------------------------------------------
#define QPITCH 272
#define QTILE  (128 * QPITCH)          // 34816
#define KPITCH 272
#define KTILE  (64 * KPITCH)           // 17408
#define VPITCH 144
#define VTILE  (128 * VPITCH)          // 18432
#define BUFOFF (2 * QTILE)             // 69632
#define BUFSZ  (2 * KTILE + 2 * VTILE) // 71680
#define FSMEM  (BUFOFF + 2 * BUFSZ)    // 212992

__global__ __launch_bounds__(256, 1) void flash_kernel()
{
    const int qt = (int)gridDim.x - 1 - (int)blockIdx.x;   // heavy tiles first
    const int h  = blockIdx.y;
    extern __shared__ char sm[];
    const uint32_t sb = smem_u32(sm);
    const int tid = threadIdx.x, lane = tid & 31, wid = tid >> 5;
    const int m0 = qt * 128;
    const int kvh = h >> 2;
    const int nkt = 2 * qt + 2;

    {
        const __nv_bfloat16* qsrc[2] = {g_qh + (size_t)m0 * DIM + h * HD,
                                        g_ql + (size_t)m0 * DIM + h * HD};
        #pragma unroll
        for (int t = 0; t < 2; t++)
            #pragma unroll
            for (int j = 0; j < 8; j++) {
                int linear = tid + j * 256;
                int row = linear >> 4, c = linear & 15;
                uint4 v = *(const uint4*)(qsrc[t] + (size_t)row * DIM + c * 8);
                *(uint4*)(sm + t * QTILE + row * QPITCH + c * 16) = v;
            }
    }

    #define ISSUE_TILE(KT, B)                                                     \
        {                                                                         \
            const uint32_t kb = sb + BUFOFF + (B) * BUFSZ;                        \
            const size_t krow0 = (size_t)(KT) * 64;                               \
            _Pragma("unroll")                                                     \
            for (int j = 0; j < 4; j++) {                                         \
                int linear = tid + j * 256;                                       \
                int row = linear >> 4, c = linear & 15;                           \
                size_t go = (krow0 + row) * KVD + kvh * HD + c * 8;               \
                cpa16(kb + row * KPITCH + c * 16, g_kh + go);                     \
                cpa16(kb + KTILE + row * KPITCH + c * 16, g_kl + go);             \
            }                                                                     \
            _Pragma("unroll")                                                     \
            for (int j = 0; j < 4; j++) {                                         \
                int linear = tid + j * 256;                                       \
                int row = linear >> 3, c = linear & 7;                            \
                size_t go = (size_t)(kvh * 128 + row) * SQ + krow0 + c * 8;       \
                cpa16(kb + 2 * KTILE + row * VPITCH + c * 16, g_vth + go);        \
                cpa16(kb + 2 * KTILE + VTILE + row * VPITCH + c * 16, g_vtl + go);\
            }                                                                     \
            asm volatile("cp.async.commit_group;" ::: "memory");                  \
        }

    ISSUE_TILE(0, 0);

    float O[16][4];
    #pragma unroll
    for (int i = 0; i < 16; i++)
        #pragma unroll
        for (int e = 0; e < 4; e++) O[i][e] = 0.f;
    float mrow[2] = {-1e30f, -1e30f};
    float lrow[2] = {0.f, 0.f};

    const uint32_t aH_ = sb + (uint32_t)((wid * 16 + (lane & 15)) * QPITCH + (lane >> 4) * 16);
    const uint32_t aL_ = aH_ + QTILE;
    const uint32_t bOffK = (uint32_t)(((lane & 7) + ((lane >> 4) * 8)) * KPITCH + ((lane >> 3) & 1) * 16);
    const uint32_t bOffV = (uint32_t)(((lane & 7) + ((lane >> 4) * 8)) * VPITCH + ((lane >> 3) & 1) * 16);

    for (int kt = 0; kt < nkt; kt++) {
        const int cur = kt & 1;
        asm volatile("cp.async.wait_group 0;" ::: "memory");
        __syncthreads();
        if (kt + 1 < nkt) ISSUE_TILE(kt + 1, 1 - cur);

        const uint32_t kB = sb + BUFOFF + cur * BUFSZ + bOffK;
        const uint32_t vB = sb + BUFOFF + cur * BUFSZ + 2 * KTILE + bOffV;

        // ---- S = Qs * K^T (3-term), 128x64 ----
        float s[8][4];
        #pragma unroll
        for (int i = 0; i < 8; i++)
            #pragma unroll
            for (int e = 0; e < 4; e++) s[i][e] = 0.f;

        #pragma unroll
        for (int kc = 0; kc < 8; kc++) {
            uint32_t aH[4], aL[4];
            ldm4(aH, aH_ + kc * 32);
            ldm4(aL, aL_ + kc * 32);
            #pragma unroll
            for (int np = 0; np < 4; np++) {
                uint32_t bH[4], bL[4];
                ldm4(bH, kB + np * (16 * KPITCH) + kc * 32);
                ldm4(bL, kB + KTILE + np * (16 * KPITCH) + kc * 32);
                mma16816(s[2 * np],     aH, bH[0], bH[1]);
                mma16816(s[2 * np + 1], aH, bH[2], bH[3]);
                mma16816(s[2 * np],     aH, bL[0], bL[1]);
                mma16816(s[2 * np + 1], aH, bL[2], bL[3]);
                mma16816(s[2 * np],     aL, bH[0], bH[1]);
                mma16816(s[2 * np + 1], aL, bH[2], bH[3]);
            }
        }

        // ---- causal mask (last two key tiles of each q-tile) ----
        if (kt >= 2 * qt) {
            const int kbase = kt * 64;
            const int rl0 = m0 + wid * 16 + (lane >> 2);
            const int cl0 = (lane & 3) * 2;
            #pragma unroll
            for (int nt = 0; nt < 8; nt++)
                #pragma unroll
                for (int e = 0; e < 4; e++) {
                    int col = kbase + nt * 8 + cl0 + (e & 1);
                    int row = rl0 + ((e >> 1) << 3);
                    if (col > row) s[nt][e] = -1e30f;
                }
        }

        // ---- online softmax (base 2) ----
        float nm[2], alpha[2];
        #pragma unroll
        for (int r = 0; r < 2; r++) {
            float tm = -1e30f;
            #pragma unroll
            for (int nt = 0; nt < 8; nt++)
                tm = fmaxf(tm, fmaxf(s[nt][2 * r], s[nt][2 * r + 1]));
            tm = fmaxf(tm, __shfl_xor_sync(0xffffffffu, tm, 1));
            tm = fmaxf(tm, __shfl_xor_sync(0xffffffffu, tm, 2));
            nm[r] = fmaxf(mrow[r], tm);
            alpha[r] = ex2f(mrow[r] - nm[r]);
            mrow[r] = nm[r];
        }
        #pragma unroll
        for (int r = 0; r < 2; r++) {
            float sum = 0.f;
            #pragma unroll
            for (int nt = 0; nt < 8; nt++) {
                float p0 = ex2f(s[nt][2 * r] - nm[r]);
                float p1 = ex2f(s[nt][2 * r + 1] - nm[r]);
                s[nt][2 * r] = p0; s[nt][2 * r + 1] = p1;
                sum += p0 + p1;
            }
            sum += __shfl_xor_sync(0xffffffffu, sum, 1);
            sum += __shfl_xor_sync(0xffffffffu, sum, 2);
            lrow[r] = lrow[r] * alpha[r] + sum;
        }
        #pragma unroll
        for (int nt = 0; nt < 16; nt++) {
            O[nt][0] *= alpha[0]; O[nt][1] *= alpha[0];
            O[nt][2] *= alpha[1]; O[nt][3] *= alpha[1];
        }

        // ---- PV: O += P * V (3-term), P from registers ----
        #pragma unroll
        for (int kk = 0; kk < 4; kk++) {
            uint32_t pH[4], pL[4];
            split2(s[2 * kk][0],     s[2 * kk][1],     pH[0], pL[0]);
            split2(s[2 * kk][2],     s[2 * kk][3],     pH[1], pL[1]);
            split2(s[2 * kk + 1][0], s[2 * kk + 1][1], pH[2], pL[2]);
            split2(s[2 * kk + 1][2], s[2 * kk + 1][3], pH[3], pL[3]);
            #pragma unroll
            for (int np = 0; np < 8; np++) {
                uint32_t bH[4], bL[4];
                ldm4(bH, vB + np * (16 * VPITCH) + kk * 32);
                ldm4(bL, vB + VTILE + np * (16 * VPITCH) + kk * 32);
                mma16816(O[2 * np],     pH, bH[0], bH[1]);
                mma16816(O[2 * np + 1], pH, bH[2], bH[3]);
                mma16816(O[2 * np],     pH, bL[0], bL[1]);
                mma16816(O[2 * np + 1], pH, bL[2], bL[3]);
                mma16816(O[2 * np],     pL, bH[0], bH[1]);
                mma16816(O[2 * np + 1], pL, bH[2], bH[3]);
            }
        }
    }
    #undef ISSUE_TILE

    // ---- epilogue: O/l -> split bf16 into g_ah/g_al ----
    const float inv0 = 1.f / lrow[0], inv1 = 1.f / lrow[1];
    const int row0 = m0 + wid * 16 + (lane >> 2);
    #pragma unroll
    for (int nt = 0; nt < 16; nt++) {
        const int col = h * HD + nt * 8 + (lane & 3) * 2;
        uint32_t hp, lp;
        split2(O[nt][0] * inv0, O[nt][1] * inv0, hp, lp);
        *(uint32_t*)(g_ah + (size_t)row0 * DIM + col) = hp;
        *(uint32_t*)(g_al + (size_t)row0 * DIM + col) = lp;
        split2(O[nt][2] * inv1, O[nt][3] * inv1, hp, lp);
        *(uint32_t*)(g_ah + (size_t)(row0 + 8) * DIM + col) = hp;
        *(uint32_t*)(g_al + (size_t)(row0 + 8) * DIM + col) = lp;
    }
}

// ---------------- small kernels ----------------
__global__ void split_kernel(const float* __restrict__ in, __nv_bfloat16* __restrict__ hi,
                             __nv_bfloat16* __restrict__ lo, size_t n)
{
    size_t i = (size_t)blockIdx.x * blockDim.x + threadIdx.x;
    if (i >= n) return;
    float v = in[i];
    __nv_bfloat16 h = __float2bfloat16(v);
    hi[i] = h;
    lo[i] = __float2bfloat16(v - __bfloat162float(h));
}

__global__ void transpose_split(const float* __restrict__ in, __nv_bfloat16* __restrict__ hi,
                                __nv_bfloat16* __restrict__ lo, int K, int ldin)
{
    __shared__ float t[32][33];
    int k0 = blockIdx.y * 32, n0 = blockIdx.x * 32;
    int tx = threadIdx.x, ty = threadIdx.y;
    #pragma unroll
    for (int i = 0; i < 4; i++)
        t[ty + i * 8][tx] = in[(size_t)(k0 + ty + i * 8) * ldin + n0 + tx];
    __syncthreads();
    #pragma unroll
    for (int i = 0; i < 4; i++) {
        float v = t[tx][ty + i * 8];
        __nv_bfloat16 h = __float2bfloat16(v);
        size_t o = (size_t)(n0 + ty + i * 8) * K + k0 + tx;
        hi[o] = h;
        lo[o] = __float2bfloat16(v - __bfloat162float(h));
    }
}

__global__ void rope_split(const float* __restrict__ src, int ldsrc,
                           __nv_bfloat16* __restrict__ dh, __nv_bfloat16* __restrict__ dl,
                           int lddst, int nheads, float scale,
                           const float* __restrict__ cosT, const float* __restrict__ sinT)
{
    int i = blockIdx.x * blockDim.x + threadIdx.x;
    int total = SQ * nheads * (HD / 2);
    if (i >= total) return;
    int p = i & 63;
    int rest = i >> 6;
    int h = rest % nheads;
    int s = rest / nheads;
    float c  = cosT[s * 64 + p];
    float sn = sinT[s * 64 + p];
    const float* b = src + (size_t)s * ldsrc + h * HD + 2 * p;
    float x1 = b[0], x2 = b[1];
    float o1 = (x1 * c - x2 * sn) * scale;
    float o2 = (x1 * sn + x2 * c) * scale;
    size_t o = (size_t)s * lddst + h * HD + 2 * p;
    __nv_bfloat16 h1 = __float2bfloat16(o1);
    __nv_bfloat16 h2 = __float2bfloat16(o2);
    dh[o]     = h1; dl[o]     = __float2bfloat16(o1 - __bfloat162float(h1));
    dh[o + 1] = h2; dl[o + 1] = __float2bfloat16(o2 - __bfloat162float(h2));
}

// ---------------------------------------------------------------------------
// Inputs: 0:x 1:start_pos 2:freqs_cos 3:freqs_sin 4:mask 5:wq 6:wk 7:wv 8:wo
// ---------------------------------------------------------------------------
extern "C" void kernel_launch(void* const* d_in, const int* in_sizes, int n_in,
                              void* d_out, int out_size)
{
    const float* x    = (const float*)d_in[0];
    const float* fcos = (const float*)d_in[2];
    const float* fsin = (const float*)d_in[3];
    const float* wq   = (const float*)d_in[5];
    const float* wk   = (const float*)d_in[6];
    const float* wv   = (const float*)d_in[7];
    const float* wo   = (const float*)d_in[8];
    float* out = (float*)d_out;

    float* qkv; cudaGetSymbolAddress((void**)&qkv, g_qkv);
    __nv_bfloat16 *xh, *xl, *qh, *ql, *kh, *kl, *vth, *vtl, *ah, *al, *wh, *wl, *woh, *wol;
    cudaGetSymbolAddress((void**)&xh,  g_xh);  cudaGetSymbolAddress((void**)&xl,  g_xl);
    cudaGetSymbolAddress((void**)&qh,  g_qh);  cudaGetSymbolAddress((void**)&ql,  g_ql);
    cudaGetSymbolAddress((void**)&kh,  g_kh);  cudaGetSymbolAddress((void**)&kl,  g_kl);
    cudaGetSymbolAddress((void**)&vth, g_vth); cudaGetSymbolAddress((void**)&vtl, g_vtl);
    cudaGetSymbolAddress((void**)&ah,  g_ah);  cudaGetSymbolAddress((void**)&al,  g_al);
    cudaGetSymbolAddress((void**)&wh,  g_wh);  cudaGetSymbolAddress((void**)&wl,  g_wl);
    cudaGetSymbolAddress((void**)&woh, g_woh); cudaGetSymbolAddress((void**)&wol, g_wol);

    cudaFuncSetAttribute(gemm_tc, cudaFuncAttributeMaxDynamicSharedMemorySize, GEMM_SMEM);
    cudaFuncSetAttribute(flash_kernel, cudaFuncAttributeMaxDynamicSharedMemorySize, FSMEM);

    const dim3 tb(32, 8);
    const float QSC = 0.08838834764831845f * 1.4426950408889634f;   // 1/sqrt(128)*log2(e)

    split_kernel<<<(unsigned)(((size_t)SQ * DIM + 255) / 256), 256>>>(x, xh, xl, (size_t)SQ * DIM);
    transpose_split<<<dim3(DIM / 32, DIM / 32), tb>>>(wq, wh, wl, DIM, DIM);
    transpose_split<<<dim3(KVD / 32, DIM / 32), tb>>>(wk, wh + (size_t)2048 * DIM, wl + (size_t)2048 * DIM, DIM, KVD);
    transpose_split<<<dim3(KVD / 32, DIM / 32), tb>>>(wv, wh + (size_t)2560 * DIM, wl + (size_t)2560 * DIM, DIM, KVD);
    transpose_split<<<dim3(DIM / 32, DIM / 32), tb>>>(wo, woh, wol, DIM, DIM);

    // fused QKV projection
    gemm_tc<<<dim3(3072 / 128, SQ / 128), 256, GEMM_SMEM>>>(xh, xl, DIM, wh, wl, DIM, qkv, 3072, DIM / 32);

    // RoPE + scale + split (q), RoPE + split (k), V transpose-split
    rope_split<<<(SQ * NH * 64 + 255) / 256, 256>>>(qkv, 3072, qh, ql, DIM, NH, QSC, fcos, fsin);
    rope_split<<<(SQ * NKV * 64 + 255) / 256, 256>>>(qkv + 2048, 3072, kh, kl, KVD, NKV, 1.f, fcos, fsin);
    transpose_split<<<dim3(KVD / 32, SQ / 32), tb>>>(qkv + 2560, vth, vtl, SQ, 3072);

    // fused attention (R9 config: 128-row tiles, 64-key cp.async pipeline)
    flash_kernel<<<dim3(SQ / 128, NH), 256, FSMEM>>>();

    // output projection
    gemm_tc<<<dim3(DIM / 128, SQ / 128), 256, GEMM_SMEM>>>(ah, al, DIM, woh, wol, DIM, out, DIM, DIM / 32);
}

// round 17
// speedup vs baseline: 1.0810x; 1.0810x over previous
#include <cuda_runtime.h>
#include <cuda_bf16.h>
#include <cstdint>
#include <math.h>

#define SQ   4096
#define DIM  2048
#define HD   128
#define NH   16
#define NKV  4
#define KVD  512

// ---------------- device scratch ----------------
__device__ float g_qkv[(size_t)SQ * 3072];
__device__ __nv_bfloat16 g_xh[(size_t)SQ * DIM],  g_xl[(size_t)SQ * DIM];
__device__ __nv_bfloat16 g_qh[(size_t)SQ * DIM],  g_ql[(size_t)SQ * DIM];   // scaled by 1/sqrt(hd)*log2e
__device__ __nv_bfloat16 g_kh[(size_t)SQ * KVD],  g_kl[(size_t)SQ * KVD];
__device__ __nv_bfloat16 g_vth[(size_t)KVD * SQ], g_vtl[(size_t)KVD * SQ];  // V^T [d][t]
__device__ __nv_bfloat16 g_ah[(size_t)SQ * DIM],  g_al[(size_t)SQ * DIM];
__device__ __nv_bfloat16 g_wh[(size_t)3072 * DIM], g_wl[(size_t)3072 * DIM];
__device__ __nv_bfloat16 g_woh[(size_t)DIM * DIM], g_wol[(size_t)DIM * DIM];

// ---------------- helpers ----------------
__device__ __forceinline__ uint32_t smem_u32(const void* p) {
    uint32_t a;
    asm("{ .reg .u64 t; cvta.to.shared.u64 t, %1; cvt.u32.u64 %0, t; }" : "=r"(a) : "l"(p));
    return a;
}
__device__ __forceinline__ void ldm4(uint32_t* r, uint32_t addr) {
    asm volatile("ldmatrix.sync.aligned.m8n8.x4.shared.b16 {%0,%1,%2,%3}, [%4];"
                 : "=r"(r[0]), "=r"(r[1]), "=r"(r[2]), "=r"(r[3]) : "r"(addr));
}
__device__ __forceinline__ void mma16816(float* c, const uint32_t* a, uint32_t b0, uint32_t b1) {
    asm volatile(
        "mma.sync.aligned.m16n8k16.row.col.f32.bf16.bf16.f32 "
        "{%0,%1,%2,%3}, {%4,%5,%6,%7}, {%8,%9}, {%0,%1,%2,%3};"
        : "+f"(c[0]), "+f"(c[1]), "+f"(c[2]), "+f"(c[3])
        : "r"(a[0]), "r"(a[1]), "r"(a[2]), "r"(a[3]), "r"(b0), "r"(b1));
}
__device__ __forceinline__ float ex2f(float x) {
    float r; asm("ex2.approx.ftz.f32 %0, %1;" : "=f"(r) : "f"(x)); return r;
}
__device__ __forceinline__ void split2(float c0, float c1, uint32_t& hp, uint32_t& lp) {
    asm("cvt.rn.bf16x2.f32 %0, %1, %2;" : "=r"(hp) : "f"(c1), "f"(c0));
    float h0 = __uint_as_float(hp << 16);
    float h1 = __uint_as_float(hp & 0xffff0000u);
    float l0 = c0 - h0, l1 = c1 - h1;
    asm("cvt.rn.bf16x2.f32 %0, %1, %2;" : "=r"(lp) : "f"(l1), "f"(l0));
}
__device__ __forceinline__ void cpa16(uint32_t dst, const void* src) {
    asm volatile("cp.async.cg.shared.global [%0], [%1], 16;" :: "r"(dst), "l"(src));
}

// ---------------------------------------------------------------------------
// Split-bf16 GEMM (R9 register-prefetch pipeline, term-major MMA order):
// C[M,N] fp32 = (Ah+Al)*(Bh+Bl)^T (3 terms).
// ---------------------------------------------------------------------------
#define PITCHB 80
#define OPB    (128 * PITCHB)
#define BUFB   (4 * OPB)
#define GEMM_SMEM (2 * BUFB)

__global__ __launch_bounds__(256) void gemm_tc(
    const __nv_bfloat16* __restrict__ Ah, const __nv_bfloat16* __restrict__ Al, int lda,
    const __nv_bfloat16* __restrict__ Bh, const __nv_bfloat16* __restrict__ Bl, int ldb,
    float* __restrict__ C, int ldc, int nk)
{
    extern __shared__ char smem[];
    const uint32_t sb = smem_u32(smem);
    const int tid = threadIdx.x, lane = tid & 31, wid = tid >> 5;
    const int wm = wid & 3, wn = wid >> 2;
    const int m0 = blockIdx.y * 128, n0 = blockIdx.x * 128;

    float acc[2][8][4];
    #pragma unroll
    for (int i = 0; i < 2; i++)
        #pragma unroll
        for (int j = 0; j < 8; j++)
            #pragma unroll
            for (int c = 0; c < 4; c++) acc[i][j][c] = 0.f;

    uint4 pre[4][2];
    const __nv_bfloat16* OPS[4] = {Ah, Al, Bh, Bl};

    #define LOAD_CHUNK(KC)                                                        \
        {                                                                         \
            const long long ko = (long long)(KC) * 32;                            \
            _Pragma("unroll")                                                     \
            for (int o = 0; o < 4; o++) {                                         \
                const __nv_bfloat16* P = OPS[o];                                  \
                const int ld_ = (o < 2) ? lda : ldb;                              \
                const int rb  = (o < 2) ? m0 : n0;                                \
                _Pragma("unroll")                                                 \
                for (int j = 0; j < 2; j++) {                                     \
                    int linear = tid + j * 256;                                   \
                    int row = linear >> 2, c4 = linear & 3;                       \
                    pre[o][j] = *(const uint4*)(P + (size_t)(rb + row) * ld_ + ko + c4 * 8); \
                }                                                                 \
            }                                                                     \
        }
    #define STORE_CHUNK(BUF)                                                      \
        {                                                                         \
            _Pragma("unroll")                                                     \
            for (int o = 0; o < 4; o++) {                                         \
                _Pragma("unroll")                                                 \
                for (int j = 0; j < 2; j++) {                                     \
                    int linear = tid + j * 256;                                   \
                    int row = linear >> 2, c4 = linear & 3;                       \
                    *(uint4*)(smem + (BUF) * BUFB + o * OPB + row * PITCHB + c4 * 16) = pre[o][j]; \
                }                                                                 \
            }                                                                     \
        }

    LOAD_CHUNK(0);
    STORE_CHUNK(0);
    __syncthreads();

    for (int kc = 0; kc < nk; kc++) {
        const int cur = kc & 1;
        if (kc + 1 < nk) LOAD_CHUNK(kc + 1);

        const uint32_t base = sb + cur * BUFB;
        const uint32_t aHb = base + (uint32_t)((wm * 32 + (lane & 15)) * PITCHB + (lane >> 4) * 16);
        const uint32_t aLb = aHb + OPB;
        const uint32_t bRow = (uint32_t)(wn * 64 + (lane & 7) + ((lane >> 4) * 8));
        const uint32_t bHb = base + 2 * OPB + bRow * PITCHB + (((lane >> 3) & 1) * 16);
        const uint32_t bLb = bHb + OPB;

        #pragma unroll
        for (int ks = 0; ks < 2; ks++) {
            const uint32_t ko = ks * 32;
            uint32_t aH[2][4], aL[2][4], bH[4][4], bL[4][4];
            #pragma unroll
            for (int mt = 0; mt < 2; mt++) {
                ldm4(aH[mt], aHb + mt * (16 * PITCHB) + ko);
                ldm4(aL[mt], aLb + mt * (16 * PITCHB) + ko);
            }
            #pragma unroll
            for (int np = 0; np < 4; np++) {
                ldm4(bH[np], bHb + np * (16 * PITCHB) + ko);
                ldm4(bL[np], bLb + np * (16 * PITCHB) + ko);
            }
            // term-major order: same-accumulator reuse distance = 16 MMAs
            #pragma unroll
            for (int mt = 0; mt < 2; mt++)
                #pragma unroll
                for (int np = 0; np < 4; np++) {
                    mma16816(acc[mt][2 * np],     aH[mt], bH[np][0], bH[np][1]);
                    mma16816(acc[mt][2 * np + 1], aH[mt], bH[np][2], bH[np][3]);
                }
            #pragma unroll
            for (int mt = 0; mt < 2; mt++)
                #pragma unroll
                for (int np = 0; np < 4; np++) {
                    mma16816(acc[mt][2 * np],     aH[mt], bL[np][0], bL[np][1]);
                    mma16816(acc[mt][2 * np + 1], aH[mt], bL[np][2], bL[np][3]);
                }
            #pragma unroll
            for (int mt = 0; mt < 2; mt++)
                #pragma unroll
                for (int np = 0; np < 4; np++) {
                    mma16816(acc[mt][2 * np],     aL[mt], bH[np][0], bH[np][1]);
                    mma16816(acc[mt][2 * np + 1], aL[mt], bH[np][2], bH[np][3]);
                }
        }

        if (kc + 1 < nk) {
            STORE_CHUNK((kc + 1) & 1);
            __syncthreads();
        }
    }

    #pragma unroll
    for (int mt = 0; mt < 2; mt++)
        #pragma unroll
        for (int nt = 0; nt < 8; nt++) {
            const int r0 = m0 + wm * 32 + mt * 16 + (lane >> 2);
            const int cc = n0 + wn * 64 + nt * 8 + (lane & 3) * 2;
            *(float2*)&C[(size_t)r0 * ldc + cc]       = make_float2(acc[mt][nt][0], acc[mt][nt][1]);
            *(float2*)&C[(size_t)(r0 + 8) * ldc + cc] = make_float2(acc[mt][nt][2], acc[mt][nt][3]);
        }
    #undef LOAD_CHUNK
    #undef STORE_CHUNK
}

// ---------------------------------------------------------------------------
// Flash attention (R9 config, term-major MMA order): 128-row q-tiles, 8 warps,
// 64-key K/V tiles, cp.async double-buffered.
// ---------------------------------------------------------------------------
#define QPITCH 272
#define QTILE  (128 * QPITCH)          // 34816
#define KPITCH 272
#define KTILE  (64 * KPITCH)           // 17408
#define VPITCH 144
#define VTILE  (128 * VPITCH)          // 18432
#define BUFOFF (2 * QTILE)             // 69632
#define BUFSZ  (2 * KTILE + 2 * VTILE) // 71680
#define FSMEM  (BUFOFF + 2 * BUFSZ)    // 212992

__global__ __launch_bounds__(256, 1) void flash_kernel()
{
    const int qt = (int)gridDim.x - 1 - (int)blockIdx.x;   // heavy tiles first
    const int h  = blockIdx.y;
    extern __shared__ char sm[];
    const uint32_t sb = smem_u32(sm);
    const int tid = threadIdx.x, lane = tid & 31, wid = tid >> 5;
    const int m0 = qt * 128;
    const int kvh = h >> 2;
    const int nkt = 2 * qt + 2;

    {
        const __nv_bfloat16* qsrc[2] = {g_qh + (size_t)m0 * DIM + h * HD,
                                        g_ql + (size_t)m0 * DIM + h * HD};
        #pragma unroll
        for (int t = 0; t < 2; t++)
            #pragma unroll
            for (int j = 0; j < 8; j++) {
                int linear = tid + j * 256;
                int row = linear >> 4, c = linear & 15;
                uint4 v = *(const uint4*)(qsrc[t] + (size_t)row * DIM + c * 8);
                *(uint4*)(sm + t * QTILE + row * QPITCH + c * 16) = v;
            }
    }

    #define ISSUE_TILE(KT, B)                                                     \
        {                                                                         \
            const uint32_t kb = sb + BUFOFF + (B) * BUFSZ;                        \
            const size_t krow0 = (size_t)(KT) * 64;                               \
            _Pragma("unroll")                                                     \
            for (int j = 0; j < 4; j++) {                                         \
                int linear = tid + j * 256;                                       \
                int row = linear >> 4, c = linear & 15;                           \
                size_t go = (krow0 + row) * KVD + kvh * HD + c * 8;               \
                cpa16(kb + row * KPITCH + c * 16, g_kh + go);                     \
                cpa16(kb + KTILE + row * KPITCH + c * 16, g_kl + go);             \
            }                                                                     \
            _Pragma("unroll")                                                     \
            for (int j = 0; j < 4; j++) {                                         \
                int linear = tid + j * 256;                                       \
                int row = linear >> 3, c = linear & 7;                            \
                size_t go = (size_t)(kvh * 128 + row) * SQ + krow0 + c * 8;       \
                cpa16(kb + 2 * KTILE + row * VPITCH + c * 16, g_vth + go);        \
                cpa16(kb + 2 * KTILE + VTILE + row * VPITCH + c * 16, g_vtl + go);\
            }                                                                     \
            asm volatile("cp.async.commit_group;" ::: "memory");                  \
        }

    ISSUE_TILE(0, 0);

    float O[16][4];
    #pragma unroll
    for (int i = 0; i < 16; i++)
        #pragma unroll
        for (int e = 0; e < 4; e++) O[i][e] = 0.f;
    float mrow[2] = {-1e30f, -1e30f};
    float lrow[2] = {0.f, 0.f};

    const uint32_t aH_ = sb + (uint32_t)((wid * 16 + (lane & 15)) * QPITCH + (lane >> 4) * 16);
    const uint32_t aL_ = aH_ + QTILE;
    const uint32_t bOffK = (uint32_t)(((lane & 7) + ((lane >> 4) * 8)) * KPITCH + ((lane >> 3) & 1) * 16);
    const uint32_t bOffV = (uint32_t)(((lane & 7) + ((lane >> 4) * 8)) * VPITCH + ((lane >> 3) & 1) * 16);

    for (int kt = 0; kt < nkt; kt++) {
        const int cur = kt & 1;
        asm volatile("cp.async.wait_group 0;" ::: "memory");
        __syncthreads();
        if (kt + 1 < nkt) ISSUE_TILE(kt + 1, 1 - cur);

        const uint32_t kB = sb + BUFOFF + cur * BUFSZ + bOffK;
        const uint32_t vB = sb + BUFOFF + cur * BUFSZ + 2 * KTILE + bOffV;

        // ---- S = Qs * K^T (3-term), 128x64; np processed in pairs,
        //      term-major within pair -> same-acc distance 4 MMAs ----
        float s[8][4];
        #pragma unroll
        for (int i = 0; i < 8; i++)
            #pragma unroll
            for (int e = 0; e < 4; e++) s[i][e] = 0.f;

        #pragma unroll
        for (int kc = 0; kc < 8; kc++) {
            uint32_t aH[4], aL[4];
            ldm4(aH, aH_ + kc * 32);
            ldm4(aL, aL_ + kc * 32);
            #pragma unroll
            for (int npp = 0; npp < 4; npp += 2) {
                uint32_t bH0[4], bH1[4], bL0[4], bL1[4];
                ldm4(bH0, kB + npp * (16 * KPITCH) + kc * 32);
                ldm4(bH1, kB + (npp + 1) * (16 * KPITCH) + kc * 32);
                ldm4(bL0, kB + KTILE + npp * (16 * KPITCH) + kc * 32);
                ldm4(bL1, kB + KTILE + (npp + 1) * (16 * KPITCH) + kc * 32);
                mma16816(s[2 * npp],     aH, bH0[0], bH0[1]);
                mma16816(s[2 * npp + 1], aH, bH0[2], bH0[3]);
                mma16816(s[2 * npp + 2], aH, bH1[0], bH1[1]);
                mma16816(s[2 * npp + 3], aH, bH1[2], bH1[3]);
                mma16816(s[2 * npp],     aH, bL0[0], bL0[1]);
                mma16816(s[2 * npp + 1], aH, bL0[2], bL0[3]);
                mma16816(s[2 * npp + 2], aH, bL1[0], bL1[1]);
                mma16816(s[2 * npp + 3], aH, bL1[2], bL1[3]);
                mma16816(s[2 * npp],     aL, bH0[0], bH0[1]);
                mma16816(s[2 * npp + 1], aL, bH0[2], bH0[3]);
                mma16816(s[2 * npp + 2], aL, bH1[0], bH1[1]);
                mma16816(s[2 * npp + 3], aL, bH1[2], bH1[3]);
            }
        }

        // ---- causal mask (last two key tiles of each q-tile) ----
        if (kt >= 2 * qt) {
            const int kbase = kt * 64;
            const int rl0 = m0 + wid * 16 + (lane >> 2);
            const int cl0 = (lane & 3) * 2;
            #pragma unroll
            for (int nt = 0; nt < 8; nt++)
                #pragma unroll
                for (int e = 0; e < 4; e++) {
                    int col = kbase + nt * 8 + cl0 + (e & 1);
                    int row = rl0 + ((e >> 1) << 3);
                    if (col > row) s[nt][e] = -1e30f;
                }
        }

        // ---- online softmax (base 2) ----
        float nm[2], alpha[2];
        #pragma unroll
        for (int r = 0; r < 2; r++) {
            float tm = -1e30f;
            #pragma unroll
            for (int nt = 0; nt < 8; nt++)
                tm = fmaxf(tm, fmaxf(s[nt][2 * r], s[nt][2 * r + 1]));
            tm = fmaxf(tm, __shfl_xor_sync(0xffffffffu, tm, 1));
            tm = fmaxf(tm, __shfl_xor_sync(0xffffffffu, tm, 2));
            nm[r] = fmaxf(mrow[r], tm);
            alpha[r] = ex2f(mrow[r] - nm[r]);
            mrow[r] = nm[r];
        }
        #pragma unroll
        for (int r = 0; r < 2; r++) {
            float sum = 0.f;
            #pragma unroll
            for (int nt = 0; nt < 8; nt++) {
                float p0 = ex2f(s[nt][2 * r] - nm[r]);
                float p1 = ex2f(s[nt][2 * r + 1] - nm[r]);
                s[nt][2 * r] = p0; s[nt][2 * r + 1] = p1;
                sum += p0 + p1;
            }
            sum += __shfl_xor_sync(0xffffffffu, sum, 1);
            sum += __shfl_xor_sync(0xffffffffu, sum, 2);
            lrow[r] = lrow[r] * alpha[r] + sum;
        }
        #pragma unroll
        for (int nt = 0; nt < 16; nt++) {
            O[nt][0] *= alpha[0]; O[nt][1] *= alpha[0];
            O[nt][2] *= alpha[1]; O[nt][3] *= alpha[1];
        }

        // ---- PV: O += P * V (3-term); np pairs, term-major within pair ----
        #pragma unroll
        for (int kk = 0; kk < 4; kk++) {
            uint32_t pH[4], pL[4];
            split2(s[2 * kk][0],     s[2 * kk][1],     pH[0], pL[0]);
            split2(s[2 * kk][2],     s[2 * kk][3],     pH[1], pL[1]);
            split2(s[2 * kk + 1][0], s[2 * kk + 1][1], pH[2], pL[2]);
            split2(s[2 * kk + 1][2], s[2 * kk + 1][3], pH[3], pL[3]);
            #pragma unroll
            for (int npp = 0; npp < 8; npp += 2) {
                uint32_t bH0[4], bH1[4], bL0[4], bL1[4];
                ldm4(bH0, vB + npp * (16 * VPITCH) + kk * 32);
                ldm4(bH1, vB + (npp + 1) * (16 * VPITCH) + kk * 32);
                ldm4(bL0, vB + VTILE + npp * (16 * VPITCH) + kk * 32);
                ldm4(bL1, vB + VTILE + (npp + 1) * (16 * VPITCH) + kk * 32);
                mma16816(O[2 * npp],     pH, bH0[0], bH0[1]);
                mma16816(O[2 * npp + 1], pH, bH0[2], bH0[3]);
                mma16816(O[2 * npp + 2], pH, bH1[0], bH1[1]);
                mma16816(O[2 * npp + 3], pH, bH1[2], bH1[3]);
                mma16816(O[2 * npp],     pH, bL0[0], bL0[1]);
                mma16816(O[2 * npp + 1], pH, bL0[2], bL0[3]);
                mma16816(O[2 * npp + 2], pH, bL1[0], bL1[1]);
                mma16816(O[2 * npp + 3], pH, bL1[2], bL1[3]);
                mma16816(O[2 * npp],     pL, bH0[0], bH0[1]);
                mma16816(O[2 * npp + 1], pL, bH0[2], bH0[3]);
                mma16816(O[2 * npp + 2], pL, bH1[0], bH1[1]);
                mma16816(O[2 * npp + 3], pL, bH1[2], bH1[3]);
            }
        }
    }
    #undef ISSUE_TILE

    // ---- epilogue: O/l -> split bf16 into g_ah/g_al ----
    const float inv0 = 1.f / lrow[0], inv1 = 1.f / lrow[1];
    const int row0 = m0 + wid * 16 + (lane >> 2);
    #pragma unroll
    for (int nt = 0; nt < 16; nt++) {
        const int col = h * HD + nt * 8 + (lane & 3) * 2;
        uint32_t hp, lp;
        split2(O[nt][0] * inv0, O[nt][1] * inv0, hp, lp);
        *(uint32_t*)(g_ah + (size_t)row0 * DIM + col) = hp;
        *(uint32_t*)(g_al + (size_t)row0 * DIM + col) = lp;
        split2(O[nt][2] * inv1, O[nt][3] * inv1, hp, lp);
        *(uint32_t*)(g_ah + (size_t)(row0 + 8) * DIM + col) = hp;
        *(uint32_t*)(g_al + (size_t)(row0 + 8) * DIM + col) = lp;
    }
}

// ---------------- small kernels ----------------
__global__ void split_kernel(const float* __restrict__ in, __nv_bfloat16* __restrict__ hi,
                             __nv_bfloat16* __restrict__ lo, size_t n)
{
    size_t i = (size_t)blockIdx.x * blockDim.x + threadIdx.x;
    if (i >= n) return;
    float v = in[i];
    __nv_bfloat16 h = __float2bfloat16(v);
    hi[i] = h;
    lo[i] = __float2bfloat16(v - __bfloat162float(h));
}

__global__ void transpose_split(const float* __restrict__ in, __nv_bfloat16* __restrict__ hi,
                                __nv_bfloat16* __restrict__ lo, int K, int ldin)
{
    __shared__ float t[32][33];
    int k0 = blockIdx.y * 32, n0 = blockIdx.x * 32;
    int tx = threadIdx.x, ty = threadIdx.y;
    #pragma unroll
    for (int i = 0; i < 4; i++)
        t[ty + i * 8][tx] = in[(size_t)(k0 + ty + i * 8) * ldin + n0 + tx];
    __syncthreads();
    #pragma unroll
    for (int i = 0; i < 4; i++) {
        float v = t[tx][ty + i * 8];
        __nv_bfloat16 h = __float2bfloat16(v);
        size_t o = (size_t)(n0 + ty + i * 8) * K + k0 + tx;
        hi[o] = h;
        lo[o] = __float2bfloat16(v - __bfloat162float(h));
    }
}

__global__ void rope_split(const float* __restrict__ src, int ldsrc,
                           __nv_bfloat16* __restrict__ dh, __nv_bfloat16* __restrict__ dl,
                           int lddst, int nheads, float scale,
                           const float* __restrict__ cosT, const float* __restrict__ sinT)
{
    int i = blockIdx.x * blockDim.x + threadIdx.x;
    int total = SQ * nheads * (HD / 2);
    if (i >= total) return;
    int p = i & 63;
    int rest = i >> 6;
    int h = rest % nheads;
    int s = rest / nheads;
    float c  = cosT[s * 64 + p];
    float sn = sinT[s * 64 + p];
    const float* b = src + (size_t)s * ldsrc + h * HD + 2 * p;
    float x1 = b[0], x2 = b[1];
    float o1 = (x1 * c - x2 * sn) * scale;
    float o2 = (x1 * sn + x2 * c) * scale;
    size_t o = (size_t)s * lddst + h * HD + 2 * p;
    __nv_bfloat16 h1 = __float2bfloat16(o1);
    __nv_bfloat16 h2 = __float2bfloat16(o2);
    dh[o]     = h1; dl[o]     = __float2bfloat16(o1 - __bfloat162float(h1));
    dh[o + 1] = h2; dl[o + 1] = __float2bfloat16(o2 - __bfloat162float(h2));
}

// ---------------------------------------------------------------------------
// Inputs: 0:x 1:start_pos 2:freqs_cos 3:freqs_sin 4:mask 5:wq 6:wk 7:wv 8:wo
// ---------------------------------------------------------------------------
extern "C" void kernel_launch(void* const* d_in, const int* in_sizes, int n_in,
                              void* d_out, int out_size)
{
    const float* x    = (const float*)d_in[0];
    const float* fcos = (const float*)d_in[2];
    const float* fsin = (const float*)d_in[3];
    const float* wq   = (const float*)d_in[5];
    const float* wk   = (const float*)d_in[6];
    const float* wv   = (const float*)d_in[7];
    const float* wo   = (const float*)d_in[8];
    float* out = (float*)d_out;

    float* qkv; cudaGetSymbolAddress((void**)&qkv, g_qkv);
    __nv_bfloat16 *xh, *xl, *qh, *ql, *kh, *kl, *vth, *vtl, *ah, *al, *wh, *wl, *woh, *wol;
    cudaGetSymbolAddress((void**)&xh,  g_xh);  cudaGetSymbolAddress((void**)&xl,  g_xl);
    cudaGetSymbolAddress((void**)&qh,  g_qh);  cudaGetSymbolAddress((void**)&ql,  g_ql);
    cudaGetSymbolAddress((void**)&kh,  g_kh);  cudaGetSymbolAddress((void**)&kl,  g_kl);
    cudaGetSymbolAddress((void**)&vth, g_vth); cudaGetSymbolAddress((void**)&vtl, g_vtl);
    cudaGetSymbolAddress((void**)&ah,  g_ah);  cudaGetSymbolAddress((void**)&al,  g_al);
    cudaGetSymbolAddress((void**)&wh,  g_wh);  cudaGetSymbolAddress((void**)&wl,  g_wl);
    cudaGetSymbolAddress((void**)&woh, g_woh); cudaGetSymbolAddress((void**)&wol, g_wol);

    cudaFuncSetAttribute(gemm_tc, cudaFuncAttributeMaxDynamicSharedMemorySize, GEMM_SMEM);
    cudaFuncSetAttribute(flash_kernel, cudaFuncAttributeMaxDynamicSharedMemorySize, FSMEM);

    const dim3 tb(32, 8);
    const float QSC = 0.08838834764831845f * 1.4426950408889634f;   // 1/sqrt(128)*log2(e)

    split_kernel<<<(unsigned)(((size_t)SQ * DIM + 255) / 256), 256>>>(x, xh, xl, (size_t)SQ * DIM);
    transpose_split<<<dim3(DIM / 32, DIM / 32), tb>>>(wq, wh, wl, DIM, DIM);
    transpose_split<<<dim3(KVD / 32, DIM / 32), tb>>>(wk, wh + (size_t)2048 * DIM, wl + (size_t)2048 * DIM, DIM, KVD);
    transpose_split<<<dim3(KVD / 32, DIM / 32), tb>>>(wv, wh + (size_t)2560 * DIM, wl + (size_t)2560 * DIM, DIM, KVD);
    transpose_split<<<dim3(DIM / 32, DIM / 32), tb>>>(wo, woh, wol, DIM, DIM);

    // fused QKV projection
    gemm_tc<<<dim3(3072 / 128, SQ / 128), 256, GEMM_SMEM>>>(xh, xl, DIM, wh, wl, DIM, qkv, 3072, DIM / 32);

    // RoPE + scale + split (q), RoPE + split (k), V transpose-split
    rope_split<<<(SQ * NH * 64 + 255) / 256, 256>>>(qkv, 3072, qh, ql, DIM, NH, QSC, fcos, fsin);
    rope_split<<<(SQ * NKV * 64 + 255) / 256, 256>>>(qkv + 2048, 3072, kh, kl, KVD, NKV, 1.f, fcos, fsin);
    transpose_split<<<dim3(KVD / 32, SQ / 32), tb>>>(qkv + 2560, vth, vtl, SQ, 3072);

    // fused attention (R9 config: 128-row tiles, 64-key cp.async pipeline)
    flash_kernel<<<dim3(SQ / 128, NH), 256, FSMEM>>>();

    // output projection
    gemm_tc<<<dim3(DIM / 128, SQ / 128), 256, GEMM_SMEM>>>(ah, al, DIM, woh, wol, DIM, out, DIM, DIM / 32);
}